// round 16
// baseline (speedup 1.0000x reference)
#include <cuda_runtime.h>
#include <cuda_fp16.h>
#include <cstddef>
#include <cstdint>

// Problem constants
#define BB    8
#define NN    2048
#define FIN   256
#define FOUT  128
#define ALPHA 0.2f

#define ROWS_TOTAL (BB * NN)          // 16384
#define NT    128                     // n-tile width
#define TILES (NN / NT)               // 16
#define CHUNKS ((size_t)ROWS_TOTAL * TILES)   // 262144
#define MAXNB 31                      // idx bytes per record; byte 31 = count

// Scratch (allocation-free rule: __device__ globals)
__device__ __half2 g_Whh[ROWS_TOTAL * FOUT / 2];   // 4 MB (fp16 Wh)
__device__ float   g_s1[ROWS_TOTAL];
__device__ float   g_s2[ROWS_TOTAL];
// per (row, 128-tile) record: bytes [0..31) local neighbor idx, byte 31 = count
__device__ unsigned char g_rec[CHUNKS * 32];       // 8 MB

// ---------------------------------------------------------------------------
// cp.async helpers
// ---------------------------------------------------------------------------
__device__ __forceinline__ void cpa16(uint32_t dst, const void* src) {
    asm volatile("cp.async.cg.shared.global [%0], [%1], 16;" :: "r"(dst), "l"(src));
}
#define CP_COMMIT() asm volatile("cp.async.commit_group;")
#define CP_WAIT1()  asm volatile("cp.async.wait_group 1;")

// ---------------------------------------------------------------------------
// Kernel 0: compress A into per-(row,128-tile) records (R8-proven inner loop).
// Grid deliberately sized to 4 CTAs/SM so one wh CTA (256 thr, 160 KB smem)
// can be co-resident on every SM -> compress (DRAM) and wh (FMA) truly overlap
// as parallel graph branches.
// ---------------------------------------------------------------------------
__global__ void __launch_bounds__(256) gat_compress_kernel(const float* __restrict__ A)
{
    const int lane = threadIdx.x & 31;
    const unsigned warp_global = (blockIdx.x * blockDim.x + threadIdx.x) >> 5;
    const unsigned nwarps = (gridDim.x * blockDim.x) >> 5;
    const unsigned lt  = (1u << lane) - 1u;
    const unsigned bit = 1u << lane;

    for (size_t c = warp_global; c < CHUNKS; c += nwarps) {
        const float* base = A + c * NT;
        float v0 = base[lane];
        float v1 = base[32 + lane];
        float v2 = base[64 + lane];
        float v3 = base[96 + lane];
        unsigned m0 = __ballot_sync(0xffffffffu, v0 != 0.0f);
        unsigned m1 = __ballot_sync(0xffffffffu, v1 != 0.0f);
        unsigned m2 = __ballot_sync(0xffffffffu, v2 != 0.0f);
        unsigned m3 = __ballot_sync(0xffffffffu, v3 != 0.0f);

        const unsigned b1 = __popc(m0);
        const unsigned b2 = b1 + __popc(m1);
        const unsigned b3 = b2 + __popc(m2);
        const unsigned cnt = b3 + __popc(m3);

        unsigned char* out = g_rec + c * 32;
        if (m0 & bit) { unsigned p =      __popc(m0 & lt); if (p < MAXNB) out[p] = (unsigned char)lane; }
        if (m1 & bit) { unsigned p = b1 + __popc(m1 & lt); if (p < MAXNB) out[p] = (unsigned char)(32 + lane); }
        if (m2 & bit) { unsigned p = b2 + __popc(m2 & lt); if (p < MAXNB) out[p] = (unsigned char)(64 + lane); }
        if (m3 & bit) { unsigned p = b3 + __popc(m3 & lt); if (p < MAXNB) out[p] = (unsigned char)(96 + lane); }
        if (lane == 0) out[31] = (unsigned char)(cnt > MAXNB ? MAXNB : cnt);
    }
}

// ---------------------------------------------------------------------------
// Kernel 1: Wh = X @ W (fp32 math), fused s1/s2; Wh stored as fp16 (__half2).
// W fully resident in smem (128 KB). Warp computes 4 rows; lane owns 4 feats.
// ---------------------------------------------------------------------------
__global__ void __launch_bounds__(256) gat_wh_kernel(
    const float* __restrict__ X,
    const float* __restrict__ W,
    const float* __restrict__ a_vec)
{
    extern __shared__ float smem[];
    float* Wsm = smem;                 // 32768 floats (128 KB)
    float* Xs  = smem + FIN * FOUT;    // 8192 floats (32 KB)

    const int tid  = threadIdx.x;
    const int warp = tid >> 5;
    const int lane = tid & 31;

    {
        const float4* W4   = reinterpret_cast<const float4*>(W);
        float4*       Wsm4 = reinterpret_cast<float4*>(Wsm);
        #pragma unroll
        for (int i = 0; i < (FIN * FOUT / 4) / 256; i++)
            Wsm4[tid + i * 256] = W4[tid + i * 256];
    }
    __syncthreads();

    const int row0 = (blockIdx.x * 8 + warp) * 4;

    float* Xw = Xs + warp * (4 * FIN);
    {
        const float4* Xg  = reinterpret_cast<const float4*>(X + (size_t)row0 * FIN);
        float4*       Xw4 = reinterpret_cast<float4*>(Xw);
        #pragma unroll
        for (int i = 0; i < (4 * FIN / 4) / 32; i++)
            Xw4[lane + i * 32] = Xg[lane + i * 32];
    }
    __syncwarp();

    float acc[4][4];
    #pragma unroll
    for (int r = 0; r < 4; r++)
        #pragma unroll
        for (int j = 0; j < 4; j++) acc[r][j] = 0.0f;

    #pragma unroll 4
    for (int k = 0; k < FIN; k++) {
        float4 wv = reinterpret_cast<const float4*>(Wsm + k * FOUT)[lane];
        float xv[4];
        #pragma unroll
        for (int r = 0; r < 4; r++) xv[r] = Xw[r * FIN + k];
        #pragma unroll
        for (int r = 0; r < 4; r++) {
            acc[r][0] += xv[r] * wv.x;
            acc[r][1] += xv[r] * wv.y;
            acc[r][2] += xv[r] * wv.z;
            acc[r][3] += xv[r] * wv.w;
        }
    }

    float a1v[4], a2v[4];
    #pragma unroll
    for (int j = 0; j < 4; j++) {
        a1v[j] = __ldg(&a_vec[lane * 4 + j]);
        a2v[j] = __ldg(&a_vec[FOUT + lane * 4 + j]);
    }

    #pragma unroll
    for (int r = 0; r < 4; r++) {
        const int row = row0 + r;
        __half2 h0 = __floats2half2_rn(acc[r][0], acc[r][1]);
        __half2 h1 = __floats2half2_rn(acc[r][2], acc[r][3]);
        uint2 packed;
        packed.x = *reinterpret_cast<unsigned*>(&h0);
        packed.y = *reinterpret_cast<unsigned*>(&h1);
        reinterpret_cast<uint2*>(g_Whh + (size_t)row * (FOUT / 2))[lane] = packed;

        float p1 = acc[r][0]*a1v[0] + acc[r][1]*a1v[1] + acc[r][2]*a1v[2] + acc[r][3]*a1v[3];
        float p2 = acc[r][0]*a2v[0] + acc[r][1]*a2v[1] + acc[r][2]*a2v[2] + acc[r][3]*a2v[3];
        #pragma unroll
        for (int off = 16; off; off >>= 1) {
            p1 += __shfl_xor_sync(0xffffffffu, p1, off);
            p2 += __shfl_xor_sync(0xffffffffu, p2, off);
        }
        if (lane == 0) { g_s1[row] = p1; g_s2[row] = p2; }
    }
}

// ---------------------------------------------------------------------------
// Kernel 2: fused masked softmax + aggregation over fp16 Wh tiles.
// (verbatim R8 configuration: 512 thr, 16 warps x 4 rows, 2 x 32 KB fp16
// double buffer + 8 KB s2 = 72 KB -> 2 CTAs/SM.)
// ---------------------------------------------------------------------------
__global__ void __launch_bounds__(512) gat_attn_kernel(float* __restrict__ out)
{
    extern __shared__ float smem[];
    uint2* buf[2] = { reinterpret_cast<uint2*>(smem),
                      reinterpret_cast<uint2*>(smem) + NT * (FOUT / 4) };
    float* s2s = smem + 2 * NT * (FOUT / 2);

    const int tid  = threadIdx.x;
    const int warp = tid >> 5;
    const int lane = tid & 31;

    const int b  = blockIdx.x >> 5;
    const int mt = blockIdx.x & 31;
    const int m0 = mt * 64 + warp * 4;
    const int rowg0 = b * NN + m0;

    {
        const float4* s = reinterpret_cast<const float4*>(g_s2 + (size_t)b * NN);
        reinterpret_cast<float4*>(s2s)[tid] = s[tid];
    }

    float s1r[4];
    #pragma unroll
    for (int r = 0; r < 4; r++) s1r[r] = g_s1[rowg0 + r];

    float acc[4][4];
    float wsum[4];
    #pragma unroll
    for (int r = 0; r < 4; r++) {
        wsum[r] = 0.0f;
        #pragma unroll
        for (int j = 0; j < 4; j++) acc[r][j] = 0.0f;
    }

    const __half2* WhB = g_Whh + (size_t)b * NN * (FOUT / 2);

    {
        uint32_t d = (uint32_t)__cvta_generic_to_shared(buf[0]);
        const float4* s4 = reinterpret_cast<const float4*>(WhB);
        #pragma unroll
        for (int i = 0; i < 4; i++)
            cpa16(d + (uint32_t)(tid + i * 512) * 16u, s4 + tid + i * 512);
        CP_COMMIT();
    }
    unsigned recs[4];
    #pragma unroll
    for (int r = 0; r < 4; r++)
        recs[r] = g_rec[((size_t)(rowg0 + r) * TILES) * 32 + lane];

    for (int t = 0; t < TILES; t++) {
        __syncthreads();
        if (t + 1 < TILES) {
            uint32_t d = (uint32_t)__cvta_generic_to_shared(buf[(t + 1) & 1]);
            const float4* s4 =
                reinterpret_cast<const float4*>(WhB + (size_t)(t + 1) * NT * (FOUT / 2));
            #pragma unroll
            for (int i = 0; i < 4; i++)
                cpa16(d + (uint32_t)(tid + i * 512) * 16u, s4 + tid + i * 512);
        }
        CP_COMMIT();
        CP_WAIT1();
        __syncthreads();

        unsigned nrecs[4];
        if (t + 1 < TILES) {
            #pragma unroll
            for (int r = 0; r < 4; r++)
                nrecs[r] = g_rec[((size_t)(rowg0 + r) * TILES + t + 1) * 32 + lane];
        } else {
            #pragma unroll
            for (int r = 0; r < 4; r++) nrecs[r] = 0;
        }

        const uint2* B = buf[t & 1];
        const float* s2t = s2s + t * NT;

        #pragma unroll
        for (int r = 0; r < 4; r++) {
            const unsigned rec = recs[r];
            const int cnt = __shfl_sync(0xffffffffu, (int)rec, 31);
            if (cnt == 0) continue;

            float w = 0.0f;
            const int ri = (int)(rec & 127u);
            if (lane < cnt) {
                float e = s1r[r] + s2t[ri];
                e = fmaxf(e, ALPHA * e);              // leaky relu
                w = __expf(e);
            }
            wsum[r] += w;

            for (int i = 0; i < cnt; i++) {
                const float wn = __shfl_sync(0xffffffffu, w, i);
                const int   ni = __shfl_sync(0xffffffffu, ri, i);
                uint2 hv = B[(size_t)ni * 32 + lane];
                float2 f0 = __half22float2(*reinterpret_cast<__half2*>(&hv.x));
                float2 f1 = __half22float2(*reinterpret_cast<__half2*>(&hv.y));
                acc[r][0] += wn * f0.x;
                acc[r][1] += wn * f0.y;
                acc[r][2] += wn * f1.x;
                acc[r][3] += wn * f1.y;
            }
        }
        #pragma unroll
        for (int r = 0; r < 4; r++) recs[r] = nrecs[r];
    }

    #pragma unroll
    for (int r = 0; r < 4; r++) {
        float tsum = wsum[r];
        #pragma unroll
        for (int off = 16; off; off >>= 1)
            tsum += __shfl_xor_sync(0xffffffffu, tsum, off);
        const float inv = 1.0f / tsum;
        float4 o = make_float4(acc[r][0] * inv, acc[r][1] * inv,
                               acc[r][2] * inv, acc[r][3] * inv);
        reinterpret_cast<float4*>(out + ((size_t)rowg0 + r) * FOUT)[lane] = o;
    }
}

// ---------------------------------------------------------------------------
// Launch: compress (4 CTAs/SM, zero smem) and wh (1 CTA/SM, 160 KB smem) are
// resource-complementary AND now residency-compatible -> parallel branches.
// ---------------------------------------------------------------------------
extern "C" void kernel_launch(void* const* d_in, const int* in_sizes, int n_in,
                              void* d_out, int out_size)
{
    const float* X = (const float*)d_in[0];
    const float* A = (const float*)d_in[1];
    const float* W = (const float*)d_in[2];
    const float* a = (const float*)d_in[3];
    float* out = (float*)d_out;

    const size_t smemWh   = (size_t)(FIN * FOUT + 8 * 4 * FIN) * sizeof(float); // 160 KB
    const size_t smemAttn = (size_t)(2 * NT * (FOUT / 2) + NN) * sizeof(float); // 72 KB

    cudaFuncSetAttribute(gat_wh_kernel,
                         cudaFuncAttributeMaxDynamicSharedMemorySize, (int)smemWh);
    cudaFuncSetAttribute(gat_attn_kernel,
                         cudaFuncAttributeMaxDynamicSharedMemorySize, (int)smemAttn);

    cudaStream_t s2;
    cudaEvent_t eFork, eJoin;
    cudaStreamCreateWithFlags(&s2, cudaStreamNonBlocking);
    cudaEventCreateWithFlags(&eFork, cudaEventDisableTiming);
    cudaEventCreateWithFlags(&eJoin, cudaEventDisableTiming);

    // fork: side stream joins the capture of the main stream
    cudaEventRecord(eFork, 0);
    cudaStreamWaitEvent(s2, eFork, 0);

    // 592 CTAs = 4/SM -> leaves thread slots for wh's 1 CTA/SM on every SM
    gat_compress_kernel<<<592, 256, 0, s2>>>(A);              // branch A (DRAM)
    gat_wh_kernel<<<ROWS_TOTAL / 32, 256, smemWh>>>(X, W, a); // branch B (FMA)

    // join: attn depends on both
    cudaEventRecord(eJoin, s2);
    cudaStreamWaitEvent(0, eJoin, 0);

    gat_attn_kernel<<<BB * (NN / 64), 512, smemAttn>>>(out);
}

// round 17
// speedup vs baseline: 1.0208x; 1.0208x over previous
#include <cuda_runtime.h>
#include <cuda_fp16.h>
#include <mma.h>
#include <cstddef>
#include <cstdint>

using namespace nvcuda;

// Problem constants
#define BB    8
#define NN    2048
#define FIN   256
#define FOUT  128
#define ALPHA 0.2f

#define ROWS_TOTAL (BB * NN)          // 16384
#define NT    128                     // n-tile width
#define TILES (NN / NT)               // 16
#define CHUNKS ((size_t)ROWS_TOTAL * TILES)   // 262144
#define MAXNB 31                      // idx bytes per record; byte 31 = count

// Scratch (allocation-free rule: __device__ globals)
__device__ __half2 g_Whh[ROWS_TOTAL * FOUT / 2];   // 4 MB (fp16 Wh)
__device__ float   g_s1[ROWS_TOTAL];
__device__ float   g_s2[ROWS_TOTAL];
__device__ float   g_Wa[2 * FIN];                  // W@a1 (256) then W@a2 (256)
// per (row, 128-tile) record: bytes [0..31) local neighbor idx, byte 31 = count
__device__ unsigned char g_rec[CHUNKS * 32];       // 8 MB

// ---------------------------------------------------------------------------
// cp.async helpers
// ---------------------------------------------------------------------------
__device__ __forceinline__ void cpa16(uint32_t dst, const void* src) {
    asm volatile("cp.async.cg.shared.global [%0], [%1], 16;" :: "r"(dst), "l"(src));
}
#define CP_COMMIT() asm volatile("cp.async.commit_group;")
#define CP_WAIT1()  asm volatile("cp.async.wait_group 1;")

// ---------------------------------------------------------------------------
// Kernel 0: compress A into per-(row,128-tile) records (R8-proven, 2048 CTAs).
// ---------------------------------------------------------------------------
__global__ void __launch_bounds__(256) gat_compress_kernel(const float* __restrict__ A)
{
    const int lane = threadIdx.x & 31;
    const unsigned warp_global = (blockIdx.x * blockDim.x + threadIdx.x) >> 5;
    const unsigned nwarps = (gridDim.x * blockDim.x) >> 5;
    const unsigned lt  = (1u << lane) - 1u;
    const unsigned bit = 1u << lane;

    for (size_t c = warp_global; c < CHUNKS; c += nwarps) {
        const float* base = A + c * NT;
        float v0 = base[lane];
        float v1 = base[32 + lane];
        float v2 = base[64 + lane];
        float v3 = base[96 + lane];
        unsigned m0 = __ballot_sync(0xffffffffu, v0 != 0.0f);
        unsigned m1 = __ballot_sync(0xffffffffu, v1 != 0.0f);
        unsigned m2 = __ballot_sync(0xffffffffu, v2 != 0.0f);
        unsigned m3 = __ballot_sync(0xffffffffu, v3 != 0.0f);

        const unsigned b1 = __popc(m0);
        const unsigned b2 = b1 + __popc(m1);
        const unsigned b3 = b2 + __popc(m2);
        const unsigned cnt = b3 + __popc(m3);

        unsigned char* out = g_rec + c * 32;
        if (m0 & bit) { unsigned p =      __popc(m0 & lt); if (p < MAXNB) out[p] = (unsigned char)lane; }
        if (m1 & bit) { unsigned p = b1 + __popc(m1 & lt); if (p < MAXNB) out[p] = (unsigned char)(32 + lane); }
        if (m2 & bit) { unsigned p = b2 + __popc(m2 & lt); if (p < MAXNB) out[p] = (unsigned char)(64 + lane); }
        if (m3 & bit) { unsigned p = b3 + __popc(m3 & lt); if (p < MAXNB) out[p] = (unsigned char)(96 + lane); }
        if (lane == 0) out[31] = (unsigned char)(cnt > MAXNB ? MAXNB : cnt);
    }
}

// ---------------------------------------------------------------------------
// Kernel 1a: Wa1 = W @ a1, Wa2 = W @ a2  (exact fp32; 1 CTA, thread k = row k)
// ---------------------------------------------------------------------------
__global__ void __launch_bounds__(256) gat_wvec_kernel(
    const float* __restrict__ W, const float* __restrict__ a_vec)
{
    const int k = threadIdx.x;            // 0..255
    float s1 = 0.f, s2 = 0.f;
    #pragma unroll 8
    for (int o = 0; o < FOUT; o++) {
        float w = W[k * FOUT + o];
        s1 += w * a_vec[o];
        s2 += w * a_vec[FOUT + o];
    }
    g_Wa[k] = s1;
    g_Wa[FIN + k] = s2;
}

// ---------------------------------------------------------------------------
// Kernel 1b: s1[row] = X[row]·Wa1, s2[row] = X[row]·Wa2  (warp per row, fp32)
// ---------------------------------------------------------------------------
__global__ void __launch_bounds__(256) gat_s_kernel(const float* __restrict__ X)
{
    const int warp = threadIdx.x >> 5;
    const int lane = threadIdx.x & 31;
    const int row  = blockIdx.x * 8 + warp;

    const float4* x4 = reinterpret_cast<const float4*>(X + (size_t)row * FIN);
    const float4* w1 = reinterpret_cast<const float4*>(g_Wa);
    const float4* w2 = reinterpret_cast<const float4*>(g_Wa + FIN);

    float4 xa = x4[lane], xb = x4[lane + 32];
    float4 p1a = w1[lane], p1b = w1[lane + 32];
    float4 p2a = w2[lane], p2b = w2[lane + 32];

    float s1 = xa.x*p1a.x + xa.y*p1a.y + xa.z*p1a.z + xa.w*p1a.w
             + xb.x*p1b.x + xb.y*p1b.y + xb.z*p1b.z + xb.w*p1b.w;
    float s2 = xa.x*p2a.x + xa.y*p2a.y + xa.z*p2a.z + xa.w*p2a.w
             + xb.x*p2b.x + xb.y*p2b.y + xb.z*p2b.z + xb.w*p2b.w;
    #pragma unroll
    for (int off = 16; off; off >>= 1) {
        s1 += __shfl_xor_sync(0xffffffffu, s1, off);
        s2 += __shfl_xor_sync(0xffffffffu, s2, off);
    }
    if (lane == 0) { g_s1[row] = s1; g_s2[row] = s2; }
}

// ---------------------------------------------------------------------------
// Kernel 1c: Wh = X @ W via WMMA tf32 (m16n16k8), output fp16 g_Whh.
// CTA = 128 rows x 128 cols, K=256 in 8 chunks of 32, cp.async double buffer.
// 8 warps in a 4x2 (m,n) grid; warp tile 32x64 (2x4 fragments).
// ---------------------------------------------------------------------------
#define XS_LD 40          // X tile: 128 x 32 fp32, ld 40  (5120 floats)
#define WS_LD 136         // W tile: 32 x 128 fp32, ld 136 (4352 floats)
#define BUF_F (128 * XS_LD + 32 * WS_LD)   // 9472 floats per buffer
#define EPI_LD 72         // epilogue staging: per warp 32 x 72 fp32

__global__ void __launch_bounds__(256) gat_wh_tc_kernel(
    const float* __restrict__ X, const float* __restrict__ W)
{
    extern __shared__ float smem[];       // 2 * BUF_F floats = 75776 B
    const uint32_t su = (uint32_t)__cvta_generic_to_shared(smem);

    const int tid  = threadIdx.x;
    const int warp = tid >> 5;
    const int blk0 = blockIdx.x * 128;    // global row base
    const int mw = warp >> 1, nw = warp & 1;   // 4x2 warp grid

    // stage chunk kc into buffer b
    auto stage = [&](int kc, int b) {
        const uint32_t xb = su + (uint32_t)(b * BUF_F) * 4u;
        const uint32_t wb = xb + 128u * XS_LD * 4u;
        #pragma unroll
        for (int i = 0; i < 4; i++) {     // X: 1024 x 16B
            int ch = tid + i * 256, row = ch >> 3, c = ch & 7;
            cpa16(xb + (uint32_t)(row * (XS_LD * 4) + c * 16),
                  X + (size_t)(blk0 + row) * FIN + kc * 32 + c * 4);
        }
        #pragma unroll
        for (int i = 0; i < 4; i++) {     // W: 1024 x 16B
            int ch = tid + i * 256, k = ch >> 5, c = ch & 31;
            cpa16(wb + (uint32_t)(k * (WS_LD * 4) + c * 16),
                  W + (size_t)(kc * 32 + k) * FOUT + c * 4);
        }
    };

    wmma::fragment<wmma::accumulator, 16, 16, 8, float> cf[2][4];
    #pragma unroll
    for (int i = 0; i < 2; i++)
        #pragma unroll
        for (int j = 0; j < 4; j++) wmma::fill_fragment(cf[i][j], 0.0f);

    stage(0, 0);
    CP_COMMIT();

    for (int kc = 0; kc < 8; kc++) {
        __syncthreads();                       // buf[(kc+1)&1] free
        if (kc + 1 < 8) stage(kc + 1, (kc + 1) & 1);
        CP_COMMIT();
        CP_WAIT1();                            // chunk kc landed
        __syncthreads();

        const float* Xb = smem + (kc & 1) * BUF_F;
        const float* Wb = Xb + 128 * XS_LD;

        #pragma unroll
        for (int ks = 0; ks < 4; ks++) {       // 4 k-steps of 8
            wmma::fragment<wmma::matrix_a, 16, 16, 8,
                           wmma::precision::tf32, wmma::row_major> af[2];
            wmma::fragment<wmma::matrix_b, 16, 16, 8,
                           wmma::precision::tf32, wmma::row_major> bf[4];
            #pragma unroll
            for (int i = 0; i < 2; i++) {
                wmma::load_matrix_sync(af[i],
                    Xb + (mw * 32 + i * 16) * XS_LD + ks * 8, XS_LD);
                #pragma unroll
                for (int e = 0; e < af[i].num_elements; e++)
                    af[i].x[e] = wmma::__float_to_tf32(af[i].x[e]);
            }
            #pragma unroll
            for (int j = 0; j < 4; j++) {
                wmma::load_matrix_sync(bf[j],
                    Wb + ks * 8 * WS_LD + nw * 64 + j * 16, WS_LD);
                #pragma unroll
                for (int e = 0; e < bf[j].num_elements; e++)
                    bf[j].x[e] = wmma::__float_to_tf32(bf[j].x[e]);
            }
            #pragma unroll
            for (int i = 0; i < 2; i++)
                #pragma unroll
                for (int j = 0; j < 4; j++)
                    wmma::mma_sync(cf[i][j], af[i], bf[j], cf[i][j]);
        }
    }

    // Epilogue: stage fp32 C to smem, convert to fp16, coalesced uint4 stores
    __syncthreads();
    float* stg = smem + warp * (32 * EPI_LD);
    #pragma unroll
    for (int i = 0; i < 2; i++)
        #pragma unroll
        for (int j = 0; j < 4; j++)
            wmma::store_matrix_sync(stg + i * 16 * EPI_LD + j * 16, cf[i][j],
                                    EPI_LD, wmma::mem_row_major);
    __syncthreads();

    uint4* gW = reinterpret_cast<uint4*>(g_Whh);
    #pragma unroll
    for (int i = 0; i < 8; i++) {             // 2048 x 16B chunks
        int ch = tid + i * 256;
        int row = ch >> 4, c4 = ch & 15;      // chunk = 8 cols starting c4*8
        const float* src = smem + ((row >> 5) * 2 + (c4 >> 3)) * (32 * EPI_LD)
                         + (row & 31) * EPI_LD + (c4 & 7) * 8;
        __half2 h0 = __floats2half2_rn(src[0], src[1]);
        __half2 h1 = __floats2half2_rn(src[2], src[3]);
        __half2 h2 = __floats2half2_rn(src[4], src[5]);
        __half2 h3 = __floats2half2_rn(src[6], src[7]);
        uint4 v;
        v.x = *reinterpret_cast<unsigned*>(&h0);
        v.y = *reinterpret_cast<unsigned*>(&h1);
        v.z = *reinterpret_cast<unsigned*>(&h2);
        v.w = *reinterpret_cast<unsigned*>(&h3);
        gW[(size_t)(blk0 + row) * 16 + c4] = v;
    }
}

// ---------------------------------------------------------------------------
// Kernel 2: fused masked softmax + aggregation over fp16 Wh tiles.
// (verbatim R8: 512 thr, 16 warps x 4 rows, 2 x 32 KB fp16 buffers + 8 KB s2.)
// ---------------------------------------------------------------------------
__global__ void __launch_bounds__(512) gat_attn_kernel(float* __restrict__ out)
{
    extern __shared__ float smem[];
    uint2* buf[2] = { reinterpret_cast<uint2*>(smem),
                      reinterpret_cast<uint2*>(smem) + NT * (FOUT / 4) };
    float* s2s = smem + 2 * NT * (FOUT / 2);

    const int tid  = threadIdx.x;
    const int warp = tid >> 5;
    const int lane = tid & 31;

    const int b  = blockIdx.x >> 5;
    const int mt = blockIdx.x & 31;
    const int m0 = mt * 64 + warp * 4;
    const int rowg0 = b * NN + m0;

    {
        const float4* s = reinterpret_cast<const float4*>(g_s2 + (size_t)b * NN);
        reinterpret_cast<float4*>(s2s)[tid] = s[tid];
    }

    float s1r[4];
    #pragma unroll
    for (int r = 0; r < 4; r++) s1r[r] = g_s1[rowg0 + r];

    float acc[4][4];
    float wsum[4];
    #pragma unroll
    for (int r = 0; r < 4; r++) {
        wsum[r] = 0.0f;
        #pragma unroll
        for (int j = 0; j < 4; j++) acc[r][j] = 0.0f;
    }

    const __half2* WhB = g_Whh + (size_t)b * NN * (FOUT / 2);

    {
        uint32_t d = (uint32_t)__cvta_generic_to_shared(buf[0]);
        const float4* s4 = reinterpret_cast<const float4*>(WhB);
        #pragma unroll
        for (int i = 0; i < 4; i++)
            cpa16(d + (uint32_t)(tid + i * 512) * 16u, s4 + tid + i * 512);
        CP_COMMIT();
    }
    unsigned recs[4];
    #pragma unroll
    for (int r = 0; r < 4; r++)
        recs[r] = g_rec[((size_t)(rowg0 + r) * TILES) * 32 + lane];

    for (int t = 0; t < TILES; t++) {
        __syncthreads();
        if (t + 1 < TILES) {
            uint32_t d = (uint32_t)__cvta_generic_to_shared(buf[(t + 1) & 1]);
            const float4* s4 =
                reinterpret_cast<const float4*>(WhB + (size_t)(t + 1) * NT * (FOUT / 2));
            #pragma unroll
            for (int i = 0; i < 4; i++)
                cpa16(d + (uint32_t)(tid + i * 512) * 16u, s4 + tid + i * 512);
        }
        CP_COMMIT();
        CP_WAIT1();
        __syncthreads();

        unsigned nrecs[4];
        if (t + 1 < TILES) {
            #pragma unroll
            for (int r = 0; r < 4; r++)
                nrecs[r] = g_rec[((size_t)(rowg0 + r) * TILES + t + 1) * 32 + lane];
        } else {
            #pragma unroll
            for (int r = 0; r < 4; r++) nrecs[r] = 0;
        }

        const uint2* B = buf[t & 1];
        const float* s2t = s2s + t * NT;

        #pragma unroll
        for (int r = 0; r < 4; r++) {
            const unsigned rec = recs[r];
            const int cnt = __shfl_sync(0xffffffffu, (int)rec, 31);
            if (cnt == 0) continue;

            float w = 0.0f;
            const int ri = (int)(rec & 127u);
            if (lane < cnt) {
                float e = s1r[r] + s2t[ri];
                e = fmaxf(e, ALPHA * e);              // leaky relu
                w = __expf(e);
            }
            wsum[r] += w;

            for (int i = 0; i < cnt; i++) {
                const float wn = __shfl_sync(0xffffffffu, w, i);
                const int   ni = __shfl_sync(0xffffffffu, ri, i);
                uint2 hv = B[(size_t)ni * 32 + lane];
                float2 f0 = __half22float2(*reinterpret_cast<__half2*>(&hv.x));
                float2 f1 = __half22float2(*reinterpret_cast<__half2*>(&hv.y));
                acc[r][0] += wn * f0.x;
                acc[r][1] += wn * f0.y;
                acc[r][2] += wn * f1.x;
                acc[r][3] += wn * f1.y;
            }
        }
        #pragma unroll
        for (int r = 0; r < 4; r++) recs[r] = nrecs[r];
    }

    #pragma unroll
    for (int r = 0; r < 4; r++) {
        float tsum = wsum[r];
        #pragma unroll
        for (int off = 16; off; off >>= 1)
            tsum += __shfl_xor_sync(0xffffffffu, tsum, off);
        const float inv = 1.0f / tsum;
        float4 o = make_float4(acc[r][0] * inv, acc[r][1] * inv,
                               acc[r][2] * inv, acc[r][3] * inv);
        reinterpret_cast<float4*>(out + ((size_t)rowg0 + r) * FOUT)[lane] = o;
    }
}

// ---------------------------------------------------------------------------
extern "C" void kernel_launch(void* const* d_in, const int* in_sizes, int n_in,
                              void* d_out, int out_size)
{
    const float* X = (const float*)d_in[0];
    const float* A = (const float*)d_in[1];
    const float* W = (const float*)d_in[2];
    const float* a = (const float*)d_in[3];
    float* out = (float*)d_out;

    const size_t smemTC   = (size_t)(2 * BUF_F) * sizeof(float);               // ~74 KB
    const size_t smemAttn = (size_t)(2 * NT * (FOUT / 2) + NN) * sizeof(float); // 72 KB

    cudaFuncSetAttribute(gat_wh_tc_kernel,
                         cudaFuncAttributeMaxDynamicSharedMemorySize, (int)smemTC);
    cudaFuncSetAttribute(gat_attn_kernel,
                         cudaFuncAttributeMaxDynamicSharedMemorySize, (int)smemAttn);

    gat_compress_kernel<<<2048, 256>>>(A);
    gat_wvec_kernel<<<1, 256>>>(W, a);
    gat_s_kernel<<<ROWS_TOTAL / 8, 256>>>(X);
    gat_wh_tc_kernel<<<ROWS_TOTAL / 128, 256, smemTC>>>(X, W);
    gat_attn_kernel<<<BB * (NN / 64), 512, smemAttn>>>(out);
}